// round 2
// baseline (speedup 1.0000x reference)
#include <cuda_runtime.h>

#define BS    16384
#define NCH   8
#define HDIM  256
#define RANK  16
#define NAGG  4
#define TDIM  64
#define RCOLS 272   // (RANK+1)*RANK columns in U/b
#define NEED  256   // only rows 0..15 of the 17x16 reshape are ever used

// 512 MiB scratch: ris[b][c][a][256]  (row-major)
__device__ float g_ris[(size_t)BS * NCH * NAGG * NEED];

// ---------------------------------------------------------------------------
// Kernel 1: per-channel GEMM with fused bias.
//   For channel c, aggregator a:
//     g_ris[b][c][a][col] = sum_h nb[b][c][h] * U[c][a][h][col] + bias[c][a][col]
//   (col in [0,256); the last 16 of the 272 U columns are dead code.)
// Tiling: BM=128, BN=128 (half of one a's 256 cols), BK=16, 256 threads, 8x8/thread.
// ---------------------------------------------------------------------------
#define BM 128
#define BN 128
#define BK 16

__global__ __launch_bounds__(256) void tt_gemm_kernel(
    const float* __restrict__ nb,    // [BS][NCH][HDIM]
    const float* __restrict__ U,     // [NCH][NAGG][HDIM][RCOLS]
    const float* __restrict__ bias)  // [NCH][NAGG][1][RCOLS]
{
    const int c    = blockIdx.z;
    const int bm   = blockIdx.x;            // sample tile
    const int bn   = blockIdx.y;            // 0..7
    const int a    = bn >> 1;
    const int col0 = (bn & 1) * BN;

    __shared__ float As[BK][BM + 4];        // +4 pad: reduce store conflicts
    __shared__ float Bs[BK][BN];

    const int tid = threadIdx.x;
    const int tx  = tid & 15;               // col group (0..15)
    const int ty  = tid >> 4;               // row group (0..15)

    // A-load mapping: 2 x float4 per thread (rows arow, arow+64)
    const int arow = tid >> 2;              // 0..63
    const int ak4  = (tid & 3) * 4;         // k offset 0/4/8/12
    // B-load mapping: 2 x float4 per thread (k rows bk, bk+8)
    const int bk   = tid >> 5;              // 0..7
    const int bn4  = (tid & 31) * 4;        // 0..124

    const float* Ag = nb + ((size_t)(bm * BM) * NCH + c) * HDIM;           // + r*NCH*HDIM + k
    const float* Bg = U  + ((size_t)(c * NAGG + a) * HDIM) * RCOLS + col0; // + k*RCOLS + n

    float acc[8][8];
    #pragma unroll
    for (int i = 0; i < 8; i++)
        #pragma unroll
        for (int j = 0; j < 8; j++) acc[i][j] = 0.f;

    for (int k0 = 0; k0 < HDIM; k0 += BK) {
        #pragma unroll
        for (int half = 0; half < 2; half++) {
            int r = arow + half * 64;
            float4 v = *(const float4*)(Ag + (size_t)r * (NCH * HDIM) + k0 + ak4);
            As[ak4 + 0][r] = v.x;
            As[ak4 + 1][r] = v.y;
            As[ak4 + 2][r] = v.z;
            As[ak4 + 3][r] = v.w;
        }
        #pragma unroll
        for (int half = 0; half < 2; half++) {
            int kk = bk + half * 8;
            float4 v = *(const float4*)(Bg + (size_t)(k0 + kk) * RCOLS + bn4);
            *(float4*)&Bs[kk][bn4] = v;
        }
        __syncthreads();

        #pragma unroll
        for (int kk = 0; kk < BK; kk++) {
            float ar[8], br[8];
            *(float4*)&ar[0] = *(const float4*)&As[kk][ty * 4];
            *(float4*)&ar[4] = *(const float4*)&As[kk][64 + ty * 4];
            *(float4*)&br[0] = *(const float4*)&Bs[kk][tx * 4];
            *(float4*)&br[4] = *(const float4*)&Bs[kk][64 + tx * 4];
            #pragma unroll
            for (int i = 0; i < 8; i++)
                #pragma unroll
                for (int j = 0; j < 8; j++)
                    acc[i][j] = fmaf(ar[i], br[j], acc[i][j]);
        }
        __syncthreads();
    }

    // Epilogue: + bias, store the needed 256-col slice into g_ris
    const float* bp = bias + (size_t)(c * NAGG + a) * RCOLS + col0;
    #pragma unroll
    for (int i = 0; i < 8; i++) {
        int rloc = (i < 4) ? (ty * 4 + i) : (64 + ty * 4 + (i - 4));
        int b    = bm * BM + rloc;
        float* Cg = g_ris + (((size_t)b * NCH + c) * NAGG + a) * NEED + col0;
        #pragma unroll
        for (int jh = 0; jh < 2; jh++) {
            int cb = jh * 64 + tx * 4;
            float4 o;
            o.x = acc[i][jh * 4 + 0] + bp[cb + 0];
            o.y = acc[i][jh * 4 + 1] + bp[cb + 1];
            o.z = acc[i][jh * 4 + 2] + bp[cb + 2];
            o.w = acc[i][jh * 4 + 3] + bp[cb + 3];
            *(float4*)(Cg + cb) = o;
        }
    }
}

// ---------------------------------------------------------------------------
// Kernel 2: type init + 8-step scan + output projection.
// 16-lane group owns one (b, a); lane q holds carry[q].
//   carry0[q] = b_type[a][q] + sum_t te[b][t] * U_type[a][t][q]
//   per c:   carry[q] = sum_r carry[r]*M[r][q] + M[15][q]      (M = g_ris[b][c][a])
//   out[b][a*256+h] = b_out[a][h] + sum_r carry[r]*U_out[a][r][h]
// Grid: (BS/16, NAGG); block caches U_output[a] (16 KB) in smem.
// ---------------------------------------------------------------------------
__global__ __launch_bounds__(256) void tt_scan_kernel(
    const float* __restrict__ te,   // [BS][TDIM]
    const float* __restrict__ Ut,   // [NAGG][TDIM][RANK]
    const float* __restrict__ bt,   // [NAGG][1][RANK]
    const float* __restrict__ Uo,   // [NAGG][RANK][HDIM]
    const float* __restrict__ bo,   // [NAGG][1][HDIM]
    float* __restrict__ out)        // [BS][NAGG*HDIM]
{
    __shared__ float s_uo[RANK * HDIM];     // 16 KB: U_output for this block's a

    const int tid = threadIdx.x;
    const int a   = blockIdx.y;

    const float4* uo_g = (const float4*)(Uo + (size_t)a * RANK * HDIM);
    for (int i = tid; i < RANK * HDIM / 4; i += 256)
        ((float4*)s_uo)[i] = uo_g[i];
    __syncthreads();

    const int g = tid >> 4;                 // group within block (0..15)
    const int q = tid & 15;                 // lane within group
    const int b = blockIdx.x * 16 + g;

    // ---- init carry from type embeddings ----
    float carry = bt[a * RANK + q];
    const float* tb  = te + (size_t)b * TDIM;
    const float* utp = Ut + (size_t)(a * TDIM) * RANK + q;
    #pragma unroll
    for (int t = 0; t < TDIM; t++)
        carry = fmaf(tb[t], utp[t * RANK], carry);

    // ---- scan over channels ----
    #pragma unroll
    for (int c = 0; c < NCH; c++) {
        const float* Mp = g_ris + (((size_t)b * NCH + c) * NAGG + a) * NEED;
        float acc = 0.f, m15 = 0.f;
        #pragma unroll
        for (int r = 0; r < RANK; r++) {
            float m  = Mp[r * RANK + q];
            float cr = __shfl_sync(0xffffffffu, carry, r, 16);
            acc = fmaf(cr, m, acc);
            if (r == RANK - 1) m15 = m;     // b_rank = row 15 (index -2 of 17)
        }
        carry = acc + m15;
    }

    // ---- output projection ----
    float cr[RANK];
    #pragma unroll
    for (int r = 0; r < RANK; r++)
        cr[r] = __shfl_sync(0xffffffffu, carry, r, 16);

    float*       op  = out + (size_t)b * (NAGG * HDIM) + a * HDIM;
    const float* bop = bo + (size_t)a * HDIM;
    #pragma unroll
    for (int j = 0; j < HDIM / 16; j++) {
        int h = j * 16 + q;
        float o = bop[h];
        #pragma unroll
        for (int r = 0; r < RANK; r++)
            o = fmaf(cr[r], s_uo[r * HDIM + h], o);
        op[h] = o;
    }
}

// ---------------------------------------------------------------------------
extern "C" void kernel_launch(void* const* d_in, const int* in_sizes, int n_in,
                              void* d_out, int out_size) {
    const float* nb = (const float*)d_in[0];  // neighbour_h
    const float* te = (const float*)d_in[1];  // type_embs
    const float* U  = (const float*)d_in[2];  // U
    const float* bb = (const float*)d_in[3];  // b
    const float* Ut = (const float*)d_in[4];  // U_type
    const float* bt = (const float*)d_in[5];  // b_type
    const float* Uo = (const float*)d_in[6];  // U_output
    const float* bo = (const float*)d_in[7];  // b_output
    float* out = (float*)d_out;

    dim3 g1(BS / BM, (NEED / BN) * NAGG, NCH);   // (128, 8, 8)
    tt_gemm_kernel<<<g1, 256>>>(nb, U, bb);

    dim3 g2(BS / 16, NAGG);                      // (1024, 4)
    tt_scan_kernel<<<g2, 256>>>(te, Ut, bt, Uo, bo, out);
}

// round 4
// speedup vs baseline: 3.2907x; 3.2907x over previous
#include <cuda_runtime.h>
#include <cuda_bf16.h>
#include <cstdint>

#define BS    16384
#define NCH   8
#define HDIM  256
#define RANK  16
#define NAGG  4
#define TDIM  64
#define RCOLS 272
#define NEED  256
#define NCA   (NCH*NAGG)        // 32
#define MT    128               // samples per CTA
#define NBT   (BS/16)           // 1024 b-tiles of 16 rows

// ---------------- fragment-major operand scratch (device globals) ----------
// A frags: [c][bt(1024)][kt(16)][lane(32)] x uint4 (a0..a3) ; hi and lo
__device__ uint4 g_Afr_h[(size_t)NCH * NBT * 16 * 32];    // 67 MB
__device__ uint4 g_Afr_l[(size_t)NCH * NBT * 16 * 32];    // 67 MB
// B frags: [ca][nt(32)][kt(16)][lane(32)] x uint2 (b0,b1) ; hi and lo
__device__ uint2 g_Bfr_h[(size_t)NCA * 32 * 16 * 32];     // 4.2 MB
__device__ uint2 g_Bfr_l[(size_t)NCA * 32 * 16 * 32];     // 4.2 MB

// ---------------- helpers ---------------------------------------------------
__device__ __forceinline__ uint32_t pack_hi2(float x, float y) {
    __nv_bfloat162 p = {__float2bfloat16(x), __float2bfloat16(y)};
    return *(uint32_t*)&p;
}
__device__ __forceinline__ uint32_t pack_lo2(float x, float y) {
    float hx = __bfloat162float(__float2bfloat16(x));
    float hy = __bfloat162float(__float2bfloat16(y));
    __nv_bfloat162 p = {__float2bfloat16(x - hx), __float2bfloat16(y - hy)};
    return *(uint32_t*)&p;
}
__device__ __forceinline__ void mma16816(float* d, uint32_t a0, uint32_t a1,
                                         uint32_t a2, uint32_t a3,
                                         uint32_t b0, uint32_t b1) {
    asm volatile(
        "mma.sync.aligned.m16n8k16.row.col.f32.bf16.bf16.f32 "
        "{%0,%1,%2,%3}, {%4,%5,%6,%7}, {%8,%9}, {%0,%1,%2,%3};"
        : "+f"(d[0]), "+f"(d[1]), "+f"(d[2]), "+f"(d[3])
        : "r"(a0), "r"(a1), "r"(a2), "r"(a3), "r"(b0), "r"(b1));
}

// ---------------- prep A: nb fp32 -> hi/lo bf16 mma fragments ---------------
// frag element map (m16n8k16, A row-major m16 x k16), lane l: g=l>>2, tg=l&3
//   a0 = A[g   ][tg*2 .. +1]   a1 = A[g+8][tg*2 .. +1]
//   a2 = A[g   ][tg*2+8..+9]   a3 = A[g+8][tg*2+8..+9]
__global__ __launch_bounds__(256) void tt_prep_a(const float* __restrict__ nb) {
    size_t t = (size_t)blockIdx.x * 256 + threadIdx.x;   // [c][bt][kt][lane]
    int lane = (int)(t & 31);
    int kt   = (int)((t >> 5) & 15);
    int bt   = (int)((t >> 9) & (NBT - 1));
    int c    = (int)(t >> 19);
    int g = lane >> 2, tg = lane & 3;
    int r0 = bt * 16 + g, r1 = r0 + 8;
    int k0 = kt * 16 + tg * 2;
    const float* p0 = nb + ((size_t)r0 * NCH + c) * HDIM;
    const float* p1 = nb + ((size_t)r1 * NCH + c) * HDIM;
    float2 v0 = *(const float2*)(p0 + k0);
    float2 v1 = *(const float2*)(p1 + k0);
    float2 v2 = *(const float2*)(p0 + k0 + 8);
    float2 v3 = *(const float2*)(p1 + k0 + 8);
    uint4 h = make_uint4(pack_hi2(v0.x, v0.y), pack_hi2(v1.x, v1.y),
                         pack_hi2(v2.x, v2.y), pack_hi2(v3.x, v3.y));
    uint4 l = make_uint4(pack_lo2(v0.x, v0.y), pack_lo2(v1.x, v1.y),
                         pack_lo2(v2.x, v2.y), pack_lo2(v3.x, v3.y));
    g_Afr_h[t] = h;
    g_Afr_l[t] = l;
}

// ---------------- prep B: U fp32 -> hi/lo bf16 mma fragments ----------------
// B col-major k16 x n8, lane l: b0 = {B[tg*2][g], B[tg*2+1][g]}, b1 = +8 in k
// B[k][n] = U[ca][h=k][col=n]  (only first 256 of 272 cols used)
__global__ __launch_bounds__(256) void tt_prep_b(const float* __restrict__ U) {
    size_t t = (size_t)blockIdx.x * 256 + threadIdx.x;   // [ca][nt][kt][lane]
    int lane = (int)(t & 31);
    int kt   = (int)((t >> 5) & 15);
    int nt   = (int)((t >> 9) & 31);
    int ca   = (int)(t >> 14);
    int g = lane >> 2, tg = lane & 3;
    int n  = nt * 8 + g;
    int k0 = kt * 16 + tg * 2;
    const float* base = U + (size_t)ca * HDIM * RCOLS + n;
    float x0 = base[(size_t)(k0)     * RCOLS];
    float x1 = base[(size_t)(k0 + 1) * RCOLS];
    float x2 = base[(size_t)(k0 + 8) * RCOLS];
    float x3 = base[(size_t)(k0 + 9) * RCOLS];
    g_Bfr_h[t] = make_uint2(pack_hi2(x0, x1), pack_hi2(x2, x3));
    g_Bfr_l[t] = make_uint2(pack_lo2(x0, x1), pack_lo2(x2, x3));
}

// ---------------- fused kernel ----------------------------------------------
// smem: carry[128][4][16] 32KB | bias 1KB | P[128][264] 135KB (overlaid by
// te/Ut staging in init, Uo in output phase)
#define PPAD   264
#define OFF_BIAS  32768
#define OFF_P     34816
#define SMEM_TOT  (OFF_P + MT * PPAD * 4)   // 169984

__global__ __launch_bounds__(256, 1) void tt_fused(
    const float* __restrict__ te,   // [BS][TDIM]
    const float* __restrict__ bb,   // [NCH][NAGG][1][RCOLS]
    const float* __restrict__ Ut,   // [NAGG][TDIM][RANK]
    const float* __restrict__ bt,   // [NAGG][1][RANK]
    const float* __restrict__ Uo,   // [NAGG][RANK][HDIM]
    const float* __restrict__ bo,   // [NAGG][1][HDIM]
    float* __restrict__ out)        // [BS][NAGG*HDIM]
{
    extern __shared__ char smem[];
    float* s_carry = (float*)smem;                   // [128][4][16]
    float* s_bias  = (float*)(smem + OFF_BIAS);      // [256]
    float* s_P     = (float*)(smem + OFF_P);         // [128][264]

    const int tid  = threadIdx.x;
    const int lane = tid & 31;
    const int wid  = tid >> 5;
    const int bm   = blockIdx.x;
    const int mh   = wid >> 2;                       // m-half (64 rows)
    const int nq   = wid & 3;                        // n-quarter (64 cols)
    const int gi   = tid >> 4;                       // scan group
    const int q    = tid & 15;                       // scan lane

    // ================= init: carry0 = te @ U_type + b_type =================
    {
        float* s_Ut = s_P;                           // [4][64][16] 16KB
        float* s_te = s_P + 4096;                    // [128][64]  32KB
        for (int j = tid; j < NAGG * TDIM * RANK / 4; j += 256)
            ((float4*)s_Ut)[j] = ((const float4*)Ut)[j];
        const float4* teg = (const float4*)(te + (size_t)bm * MT * TDIM);
        for (int j = tid; j < MT * TDIM / 4; j += 256)
            ((float4*)s_te)[j] = teg[j];
        __syncthreads();
        #pragma unroll
        for (int i = 0; i < 32; i++) {
            int idx = i * 256 + tid;                 // b*64 + a*16 + qq
            int b = idx >> 6, a = (idx >> 4) & 3, qq = idx & 15;
            float cr = bt[a * RANK + qq];
            const float* tep = s_te + b * TDIM;
            const float* utp = s_Ut + a * TDIM * RANK + qq;
            #pragma unroll
            for (int tt = 0; tt < TDIM; tt++)
                cr = fmaf(tep[tt], utp[tt * RANK], cr);
            s_carry[idx] = cr;
        }
    }

    // ================= main loop over (c, a) =================
    for (int c = 0; c < NCH; c++) {
        for (int a = 0; a < NAGG; a++) {
            const int ca = c * NAGG + a;
            // ---- GEMM M=128 N=256 K=256, bf16 3-pass, accum fp32 ----
            float acc[4][8][4];
            #pragma unroll
            for (int mt = 0; mt < 4; mt++)
                #pragma unroll
                for (int nf = 0; nf < 8; nf++)
                    #pragma unroll
                    for (int e = 0; e < 4; e++) acc[mt][nf][e] = 0.f;

            const uint4* pAh = g_Afr_h +
                (((size_t)c * NBT + (size_t)bm * 8 + mh * 4) * 16) * 32 + lane;
            const uint4* pAl = g_Afr_l +
                (((size_t)c * NBT + (size_t)bm * 8 + mh * 4) * 16) * 32 + lane;
            const uint2* pBh = g_Bfr_h +
                (((size_t)ca * 32 + nq * 8) * 16) * 32 + lane;
            const uint2* pBl = g_Bfr_l +
                (((size_t)ca * 32 + nq * 8) * 16) * 32 + lane;

            #pragma unroll 1
            for (int kt = 0; kt < 16; kt++) {
                uint4 Ah[4], Al[4];
                uint2 Bh[8], Bl[8];
                #pragma unroll
                for (int mt = 0; mt < 4; mt++) {
                    Ah[mt] = pAh[(size_t)(mt * 16 + kt) * 32];
                    Al[mt] = pAl[(size_t)(mt * 16 + kt) * 32];
                }
                #pragma unroll
                for (int nf = 0; nf < 8; nf++) {
                    Bh[nf] = pBh[(size_t)(nf * 16 + kt) * 32];
                    Bl[nf] = pBl[(size_t)(nf * 16 + kt) * 32];
                }
                #pragma unroll
                for (int mt = 0; mt < 4; mt++)
                    #pragma unroll
                    for (int nf = 0; nf < 8; nf++) {
                        float* d = acc[mt][nf];
                        mma16816(d, Ah[mt].x, Ah[mt].y, Ah[mt].z, Ah[mt].w,
                                 Bh[nf].x, Bh[nf].y);
                        mma16816(d, Al[mt].x, Al[mt].y, Al[mt].z, Al[mt].w,
                                 Bh[nf].x, Bh[nf].y);
                        mma16816(d, Ah[mt].x, Ah[mt].y, Ah[mt].z, Ah[mt].w,
                                 Bl[nf].x, Bl[nf].y);
                    }
            }

            // ---- stage P + bias ----
            __syncthreads();           // prior scan done reading s_P/s_bias
            if (tid < NEED) s_bias[tid] = bb[(size_t)ca * RCOLS + tid];
            {
                int g = lane >> 2, tg = lane & 3;
                #pragma unroll
                for (int mt = 0; mt < 4; mt++) {
                    int r_lo = mh * 64 + mt * 16 + g;
                    #pragma unroll
                    for (int nf = 0; nf < 8; nf++) {
                        int col = nq * 64 + nf * 8 + tg * 2;
                        float2 lo = {acc[mt][nf][0], acc[mt][nf][1]};
                        float2 hi = {acc[mt][nf][2], acc[mt][nf][3]};
                        *(float2*)(s_P + (size_t)r_lo * PPAD + col)       = lo;
                        *(float2*)(s_P + (size_t)(r_lo + 8) * PPAD + col) = hi;
                    }
                }
            }
            __syncthreads();

            // ---- scan step: carry = carry @ M + M[15]  (M = P + bias) ----
            #pragma unroll
            for (int j = 0; j < 8; j++) {
                int b = gi * 8 + j;
                float cur = s_carry[b * 64 + a * 16 + q];
                const float* Pb = s_P + (size_t)b * PPAD;
                float accv = 0.f;
                #pragma unroll
                for (int r = 0; r < RANK; r++) {
                    float m  = Pb[r * 16 + q] + s_bias[r * 16 + q];
                    float cr = __shfl_sync(0xffffffffu, cur, r, 16);
                    accv = fmaf(cr, m, accv);
                }
                float m15 = Pb[240 + q] + s_bias[240 + q];
                s_carry[b * 64 + a * 16 + q] = accv + m15;
            }
        }
    }

    // ================= output: out = carry @ U_output + b_output =============
    __syncthreads();
    float* s_Uo = s_P;                               // [4][16][256] 64KB
    for (int j = tid; j < NAGG * RANK * HDIM / 4; j += 256)
        ((float4*)s_Uo)[j] = ((const float4*)Uo)[j];
    __syncthreads();

    for (int cb = 0; cb < NAGG; cb++) {
        float bov = bo[cb * HDIM + tid];
        const float* uop = s_Uo + cb * RANK * HDIM + tid;
        for (int b = 0; b < MT; b++) {
            const float* crp = s_carry + b * 64 + cb * 16;
            float o = bov;
            #pragma unroll
            for (int r = 0; r < RANK; r++)
                o = fmaf(crp[r], uop[r * HDIM], o);
            out[((size_t)bm * MT + b) * (NAGG * HDIM) + cb * HDIM + tid] = o;
        }
    }
}

// ---------------------------------------------------------------------------
extern "C" void kernel_launch(void* const* d_in, const int* in_sizes, int n_in,
                              void* d_out, int out_size) {
    const float* nb = (const float*)d_in[0];
    const float* te = (const float*)d_in[1];
    const float* U  = (const float*)d_in[2];
    const float* bb = (const float*)d_in[3];
    const float* Ut = (const float*)d_in[4];
    const float* bt = (const float*)d_in[5];
    const float* Uo = (const float*)d_in[6];
    const float* bo = (const float*)d_in[7];
    float* out = (float*)d_out;

    cudaFuncSetAttribute(tt_fused, cudaFuncAttributeMaxDynamicSharedMemorySize,
                         SMEM_TOT);

    tt_prep_a<<<(int)((size_t)NCH * NBT * 16 * 32 / 256), 256>>>(nb);
    tt_prep_b<<<(int)((size_t)NCA * 32 * 16 * 32 / 256), 256>>>(U);
    tt_fused<<<BS / MT, 256, SMEM_TOT>>>(te, bb, Ut, bt, Uo, bo, out);
}

// round 6
// speedup vs baseline: 3.5895x; 1.0908x over previous
#include <cuda_runtime.h>
#include <cuda_bf16.h>
#include <cstdint>

#define BS    16384
#define NCH   8
#define HDIM  256
#define RANK  16
#define NAGG  4
#define TDIM  64
#define RCOLS 272
#define NEED  256
#define NCA   (NCH*NAGG)        // 32
#define NBT   (BS/16)           // 1024 real 16-row tiles
#define NTILE 7                 // tiles per CTA (uniform)
#define NCTA  148
#define NBT_PAD (NCTA*NTILE)    // 1036 virtual tiles
#define MROWS (NTILE*16)        // 112 rows per CTA

// ---------------- fragment-major operand scratch ---------------------------
// A frags: [c][tile(1036)][kt(16)][lane(32)] x uint4 ; hi and lo
__device__ uint4 g_Afr_h[(size_t)NCH * NBT_PAD * 16 * 32];
__device__ uint4 g_Afr_l[(size_t)NCH * NBT_PAD * 16 * 32];
// B frags packed: [ca][nt(32)][kt(16)][lane(32)] x uint4 {bh0,bh1,bl0,bl1}
__device__ uint4 g_Bfr[(size_t)NCA * 32 * 16 * 32];

// ---------------- helpers ---------------------------------------------------
__device__ __forceinline__ uint32_t pack_hi2(float x, float y) {
    __nv_bfloat162 p = {__float2bfloat16(x), __float2bfloat16(y)};
    return *(uint32_t*)&p;
}
__device__ __forceinline__ uint32_t pack_lo2(float x, float y) {
    float hx = __bfloat162float(__float2bfloat16(x));
    float hy = __bfloat162float(__float2bfloat16(y));
    __nv_bfloat162 p = {__float2bfloat16(x - hx), __float2bfloat16(y - hy)};
    return *(uint32_t*)&p;
}
__device__ __forceinline__ void mma16816(float* d, uint32_t a0, uint32_t a1,
                                         uint32_t a2, uint32_t a3,
                                         uint32_t b0, uint32_t b1) {
    asm volatile(
        "mma.sync.aligned.m16n8k16.row.col.f32.bf16.bf16.f32 "
        "{%0,%1,%2,%3}, {%4,%5,%6,%7}, {%8,%9}, {%0,%1,%2,%3};"
        : "+f"(d[0]), "+f"(d[1]), "+f"(d[2]), "+f"(d[3])
        : "r"(a0), "r"(a1), "r"(a2), "r"(a3), "r"(b0), "r"(b1));
}

// ---------------- prep A: nb fp32 -> hi/lo bf16 mma fragments ---------------
__global__ __launch_bounds__(256) void tt_prep_a(const float* __restrict__ nb) {
    size_t t = (size_t)blockIdx.x * 256 + threadIdx.x;   // [c][bt(1024)][kt][lane]
    int lane = (int)(t & 31);
    int kt   = (int)((t >> 5) & 15);
    int bt   = (int)((t >> 9) & (NBT - 1));
    int c    = (int)(t >> 19);
    int g = lane >> 2, tg = lane & 3;
    int r0 = bt * 16 + g, r1 = r0 + 8;
    int k0 = kt * 16 + tg * 2;
    const float* p0 = nb + ((size_t)r0 * NCH + c) * HDIM;
    const float* p1 = nb + ((size_t)r1 * NCH + c) * HDIM;
    float2 v0 = *(const float2*)(p0 + k0);
    float2 v1 = *(const float2*)(p1 + k0);
    float2 v2 = *(const float2*)(p0 + k0 + 8);
    float2 v3 = *(const float2*)(p1 + k0 + 8);
    size_t o = (((size_t)c * NBT_PAD + bt) * 16 + kt) * 32 + lane;
    g_Afr_h[o] = make_uint4(pack_hi2(v0.x, v0.y), pack_hi2(v1.x, v1.y),
                            pack_hi2(v2.x, v2.y), pack_hi2(v3.x, v3.y));
    g_Afr_l[o] = make_uint4(pack_lo2(v0.x, v0.y), pack_lo2(v1.x, v1.y),
                            pack_lo2(v2.x, v2.y), pack_lo2(v3.x, v3.y));
}

// ---------------- prep B: U fp32 -> packed hi/lo bf16 fragments -------------
__global__ __launch_bounds__(256) void tt_prep_b(const float* __restrict__ U) {
    size_t t = (size_t)blockIdx.x * 256 + threadIdx.x;   // [ca][nt(32)][kt][lane]
    int lane = (int)(t & 31);
    int kt   = (int)((t >> 5) & 15);
    int nt   = (int)((t >> 9) & 31);
    int ca   = (int)(t >> 14);
    int g = lane >> 2, tg = lane & 3;
    int n  = nt * 8 + g;
    int k0 = kt * 16 + tg * 2;
    const float* base = U + (size_t)ca * HDIM * RCOLS + n;
    float x0 = base[(size_t)(k0)     * RCOLS];
    float x1 = base[(size_t)(k0 + 1) * RCOLS];
    float x2 = base[(size_t)(k0 + 8) * RCOLS];
    float x3 = base[(size_t)(k0 + 9) * RCOLS];
    g_Bfr[t] = make_uint4(pack_hi2(x0, x1), pack_hi2(x2, x3),
                          pack_lo2(x0, x1), pack_lo2(x2, x3));
}

// ---------------- fused kernel ----------------------------------------------
#define PPAD      264
#define OFF_BIAS  (MROWS * 64 * 4)            // carry: 112*64*4 = 28672
#define OFF_P     (OFF_BIAS + 1024)           // 29696
#define SMEM_TOT  (OFF_P + MROWS * PPAD * 4)  // 147968

__global__ __launch_bounds__(256, 1) void tt_fused(
    const float* __restrict__ te,   // [BS][TDIM]
    const float* __restrict__ bb,   // [NCH][NAGG][1][RCOLS]
    const float* __restrict__ Ut,   // [NAGG][TDIM][RANK]
    const float* __restrict__ bt,   // [NAGG][1][RANK]
    const float* __restrict__ Uo,   // [NAGG][RANK][HDIM]
    const float* __restrict__ bo,   // [NAGG][1][HDIM]
    float* __restrict__ out)        // [BS][NAGG*HDIM]
{
    extern __shared__ char smem[];
    float* s_carry = (float*)smem;                   // [112][4][16]
    float* s_bias  = (float*)(smem + OFF_BIAS);      // [256]
    float* s_P     = (float*)(smem + OFF_P);         // [112][264]

    const int tid  = threadIdx.x;
    const int lane = tid & 31;
    const int wid  = tid >> 5;                       // nq split: cols wid*32..+32
    const int bm   = blockIdx.x;
    const int gi   = tid >> 4;                       // scan group
    const int q    = tid & 15;                       // scan lane

    const int t0    = bm * NTILE;                    // first virtual tile
    const int row0  = t0 * 16;
    int nrows = BS - row0;
    nrows = nrows < 0 ? 0 : (nrows > MROWS ? MROWS : nrows);   // multiple of 16

    // ================= init: carry0 = te @ U_type + b_type =================
    {
        float* s_Ut = s_P;                           // [4][64][16] 16KB
        float* s_te = s_P + 4096;                    // [112][64]   28.7KB
        for (int j = tid; j < NAGG * TDIM * RANK / 4; j += 256)
            ((float4*)s_Ut)[j] = ((const float4*)Ut)[j];
        const float4* teg = (const float4*)(te + (size_t)row0 * TDIM);
        for (int j = tid; j < nrows * 16; j += 256)
            ((float4*)s_te)[j] = teg[j];
        __syncthreads();
        for (int idx = tid; idx < nrows * 64; idx += 256) {
            int b = idx >> 6, a = (idx >> 4) & 3, qq = idx & 15;
            float cr = bt[a * RANK + qq];
            const float* tep = s_te + b * TDIM;
            const float* utp = s_Ut + a * TDIM * RANK + qq;
            #pragma unroll
            for (int tt = 0; tt < TDIM; tt++)
                cr = fmaf(tep[tt], utp[tt * RANK], cr);
            s_carry[idx] = cr;
        }
        __syncthreads();
    }

    // ================= main loop over (c, a) =================
    for (int ca = 0; ca < NCA; ca++) {
        const int c = ca >> 2;
        const uint4* pAh = g_Afr_h + (((size_t)c * NBT_PAD + t0) * 16) * 32 + lane;
        const uint4* pAl = g_Afr_l + (((size_t)c * NBT_PAD + t0) * 16) * 32 + lane;
        const uint4* pB  = g_Bfr   + (((size_t)ca * 32 + wid * 4) * 16) * 32 + lane;

        // ---- prefetch kt=0 fragments + bias for this ca ----
        uint4 Ah[NTILE], Al[NTILE], Bq[4];
        #pragma unroll
        for (int mt = 0; mt < NTILE; mt++) {
            Ah[mt] = pAh[(size_t)(mt * 16) * 32];
            Al[mt] = pAl[(size_t)(mt * 16) * 32];
        }
        #pragma unroll
        for (int nf = 0; nf < 4; nf++)
            Bq[nf] = pB[(size_t)(nf * 16) * 32];
        float biasval = bb[(size_t)ca * RCOLS + tid];

        // ---- scan step for previous (c,a): overlaps the prefetch latency ----
        if (ca > 0) {
            const int pa = (ca - 1) & 3;
            for (int b = gi; b < nrows; b += 16) {
                float cur = s_carry[b * 64 + pa * 16 + q];
                const float* Pb = s_P + (size_t)b * PPAD;
                float accv = 0.f;
                #pragma unroll
                for (int r = 0; r < RANK; r++) {
                    float m  = Pb[r * 16 + q] + s_bias[r * 16 + q];
                    float cr = __shfl_sync(0xffffffffu, cur, r, 16);
                    accv = fmaf(cr, m, accv);
                }
                float m15 = Pb[240 + q] + s_bias[240 + q];
                s_carry[b * 64 + pa * 16 + q] = accv + m15;
            }
        }

        // ---- GEMM: M=112 N=256 K=256, bf16 3-pass ----
        float acc[NTILE][4][4];
        #pragma unroll
        for (int mt = 0; mt < NTILE; mt++)
            #pragma unroll
            for (int nf = 0; nf < 4; nf++)
                #pragma unroll
                for (int e = 0; e < 4; e++) acc[mt][nf][e] = 0.f;

        #pragma unroll 1
        for (int kt = 0; kt < 16; kt++) {
            #pragma unroll
            for (int mt = 0; mt < NTILE; mt++)
                #pragma unroll
                for (int nf = 0; nf < 4; nf++) {
                    float* d = acc[mt][nf];
                    mma16816(d, Ah[mt].x, Ah[mt].y, Ah[mt].z, Ah[mt].w,
                             Bq[nf].x, Bq[nf].y);
                    mma16816(d, Al[mt].x, Al[mt].y, Al[mt].z, Al[mt].w,
                             Bq[nf].x, Bq[nf].y);
                    mma16816(d, Ah[mt].x, Ah[mt].y, Ah[mt].z, Ah[mt].w,
                             Bq[nf].z, Bq[nf].w);
                }
            if (kt < 15) {
                #pragma unroll
                for (int mt = 0; mt < NTILE; mt++) {
                    Ah[mt] = pAh[(size_t)(mt * 16 + kt + 1) * 32];
                    Al[mt] = pAl[(size_t)(mt * 16 + kt + 1) * 32];
                }
                #pragma unroll
                for (int nf = 0; nf < 4; nf++)
                    Bq[nf] = pB[(size_t)(nf * 16 + kt + 1) * 32];
            }
        }

        __syncthreads();   // all scans of (ca-1) done before s_P/s_bias rewrite
        s_bias[tid] = biasval;
        {
            int g = lane >> 2, tg = lane & 3;
            #pragma unroll
            for (int mt = 0; mt < NTILE; mt++) {
                int r_lo = mt * 16 + g;
                #pragma unroll
                for (int nf = 0; nf < 4; nf++) {
                    int col = wid * 32 + nf * 8 + tg * 2;
                    float2 lo = {acc[mt][nf][0], acc[mt][nf][1]};
                    float2 hi = {acc[mt][nf][2], acc[mt][nf][3]};
                    *(float2*)(s_P + (size_t)r_lo * PPAD + col)       = lo;
                    *(float2*)(s_P + (size_t)(r_lo + 8) * PPAD + col) = hi;
                }
            }
        }
        __syncthreads();
    }

    // ---- final scan step (ca = 31, a = 3) ----
    for (int b = gi; b < nrows; b += 16) {
        float cur = s_carry[b * 64 + 3 * 16 + q];
        const float* Pb = s_P + (size_t)b * PPAD;
        float accv = 0.f;
        #pragma unroll
        for (int r = 0; r < RANK; r++) {
            float m  = Pb[r * 16 + q] + s_bias[r * 16 + q];
            float cr = __shfl_sync(0xffffffffu, cur, r, 16);
            accv = fmaf(cr, m, accv);
        }
        float m15 = Pb[240 + q] + s_bias[240 + q];
        s_carry[b * 64 + 3 * 16 + q] = accv + m15;
    }

    // ================= output: out = carry @ U_output + b_output ============
    __syncthreads();
    float* s_Uo = s_P;                               // [4][16][256] 64KB
    for (int j = tid; j < NAGG * RANK * HDIM / 4; j += 256)
        ((float4*)s_Uo)[j] = ((const float4*)Uo)[j];
    __syncthreads();

    for (int cb = 0; cb < NAGG; cb++) {
        float bov = bo[cb * HDIM + tid];
        const float* uop = s_Uo + cb * RANK * HDIM + tid;
        for (int b = 0; b < nrows; b++) {
            const float* crp = s_carry + b * 64 + cb * 16;
            float o = bov;
            #pragma unroll
            for (int r = 0; r < RANK; r++)
                o = fmaf(crp[r], uop[r * HDIM], o);
            out[((size_t)row0 + b) * (NAGG * HDIM) + cb * HDIM + tid] = o;
        }
    }
}

// ---------------------------------------------------------------------------
extern "C" void kernel_launch(void* const* d_in, const int* in_sizes, int n_in,
                              void* d_out, int out_size) {
    const float* nb = (const float*)d_in[0];
    const float* te = (const float*)d_in[1];
    const float* U  = (const float*)d_in[2];
    const float* bb = (const float*)d_in[3];
    const float* Ut = (const float*)d_in[4];
    const float* bt = (const float*)d_in[5];
    const float* Uo = (const float*)d_in[6];
    const float* bo = (const float*)d_in[7];
    float* out = (float*)d_out;

    cudaFuncSetAttribute(tt_fused, cudaFuncAttributeMaxDynamicSharedMemorySize,
                         SMEM_TOT);

    tt_prep_a<<<(int)((size_t)NCH * NBT * 16 * 32 / 256), 256>>>(nb);
    tt_prep_b<<<(int)((size_t)NCA * 32 * 16 * 32 / 256), 256>>>(U);
    tt_fused<<<NCTA, 256, SMEM_TOT>>>(te, bb, Ut, bt, Uo, bo, out);
}